// round 10
// baseline (speedup 1.0000x reference)
#include <cuda_runtime.h>
#include <math.h>

#define BB   128
#define LL   1024
#define HSZ  512

typedef unsigned long long ull;

__device__ float g_t0[(size_t)BB * 32 * LL];      // [B,32,L] transposed input
__device__ float g_y [(size_t)BB * 256 * LL];     // conv raw out (<=256 ch)
__device__ float g_a [(size_t)BB * 64  * LL];     // activated conv (<=64 ch)
__device__ float g_X [(size_t)BB * LL * 256];     // conv stack out [B,L,256]
__device__ float g_scale[256];
__device__ float g_shift[256];
__device__ float g_h[3][BB * HSZ];                // 3-buffer rotation
__device__ float g_c[BB * HSZ];
__device__ int   g_bar_cnt[4];                    // per row-group barriers
__device__ int   g_bar_sen[4];

__global__ void zero_state_k() {
    int i = blockIdx.x * 256 + threadIdx.x;
    if (i < BB * HSZ) { g_h[0][i] = 0.f; g_c[i] = 0.f; }
    if (i < 4) { g_bar_cnt[i] = 0; g_bar_sen[i] = 0; }
}

__global__ void transpose_in_k(const float* __restrict__ xin) {
    int idx = blockIdx.x * 256 + threadIdx.x;      // B*L*32, c fastest
    if (idx >= BB * LL * 32) return;
    int c = idx & 31;
    int bl = idx >> 5;
    int l = bl & (LL - 1);
    int b = bl >> 10;
    g_t0[((size_t)b * 32 + c) * LL + l] = xin[idx];
}

// conv1d K=7 pad=3 stride=1, [B,C,L]. grid(L/256, B, Cout/8), 128 thr.
template<int CIN>
__global__ __launch_bounds__(128) void conv1d_k(const float* __restrict__ in,
                                                const float* __restrict__ w,
                                                int Cout) {
    const int l0 = blockIdx.x * 256, b = blockIdx.y, co0 = blockIdx.z * 8;
    __shared__ float xs[32][264];
    __shared__ float ws[8][32][8];
    float acc[8][2];
#pragma unroll
    for (int i = 0; i < 8; i++) { acc[i][0] = 0.f; acc[i][1] = 0.f; }

    for (int cb = 0; cb < CIN; cb += 32) {
        __syncthreads();
        for (int e = threadIdx.x; e < 32 * 262; e += 128) {
            int ci = e / 262, jj = e - ci * 262;
            int l = l0 - 3 + jj;
            xs[ci][jj] = (l >= 0 && l < LL) ? in[((size_t)b * CIN + cb + ci) * LL + l] : 0.f;
        }
        for (int e = threadIdx.x; e < 8 * 32 * 7; e += 128) {
            int co = e / 224, r = e - co * 224;
            int ci = r / 7, k = r - ci * 7;
            ws[co][ci][k] = w[((size_t)(co0 + co) * CIN + cb + ci) * 7 + k];
        }
        __syncthreads();
        const int lt = threadIdx.x;
        for (int ci = 0; ci < 32; ci++) {
#pragma unroll
            for (int k = 0; k < 7; k++) {
                float x0 = xs[ci][lt + k];
                float x1 = xs[ci][lt + 128 + k];
#pragma unroll
                for (int co = 0; co < 8; co++) {
                    float wv = ws[co][ci][k];
                    acc[co][0] = fmaf(x0, wv, acc[co][0]);
                    acc[co][1] = fmaf(x1, wv, acc[co][1]);
                }
            }
        }
    }
#pragma unroll
    for (int co = 0; co < 8; co++) {
        g_y[((size_t)b * Cout + co0 + co) * LL + l0 + threadIdx.x]       = acc[co][0];
        g_y[((size_t)b * Cout + co0 + co) * LL + l0 + 128 + threadIdx.x] = acc[co][1];
    }
}

__global__ void bn_stats_k(const float* __restrict__ gam,
                           const float* __restrict__ bet, int C) {
    int c = blockIdx.x;
    float s = 0.f, s2 = 0.f;
    for (int i = threadIdx.x; i < BB * LL; i += 256) {
        float v = g_y[((size_t)(i >> 10) * C + c) * LL + (i & (LL - 1))];
        s += v; s2 += v * v;
    }
    __shared__ float rs[256], rq[256];
    rs[threadIdx.x] = s; rq[threadIdx.x] = s2;
    __syncthreads();
    for (int o = 128; o > 0; o >>= 1) {
        if (threadIdx.x < o) { rs[threadIdx.x] += rs[threadIdx.x + o]; rq[threadIdx.x] += rq[threadIdx.x + o]; }
        __syncthreads();
    }
    if (threadIdx.x == 0) {
        float inv = 1.f / (float)(BB * LL);
        float mean = rs[0] * inv;
        float var  = rq[0] * inv - mean * mean;
        float sc = gam[c] * rsqrtf(var + 1e-5f);
        g_scale[c] = sc;
        g_shift[c] = bet[c] - mean * sc;
    }
}

__global__ void bn_apply_k(float* __restrict__ outBCL, int C, int toBLC) {
    size_t idx = (size_t)blockIdx.x * 256 + threadIdx.x;
    if (idx >= (size_t)BB * C * LL) return;
    int l = (int)(idx & (LL - 1));
    size_t bc = idx >> 10;
    int c = (int)(bc % C);
    int b = (int)(bc / C);
    float v = fmaxf(g_y[idx] * g_scale[c] + g_shift[c], 0.f);
    if (toBLC) g_X[((size_t)b * LL + l) * 256 + c] = v;
    else       outBCL[idx] = v;
}

// ---------------------------------------------------------------------------
// Persistent LSTM sequence kernel. grid (32,4) = 128 CTAs, 256 threads (8 w).
// CTA tile: 32 rows x 64 gate cols, K=768 in 24 chunks of 32.
// Weights SMEM-resident for all 1024 steps; FFMA2 inner product; per-row-group
// (by) grid barrier each step; x-chunk prefetched under the barrier.
// ---------------------------------------------------------------------------
template<bool PROJ>
__global__ __launch_bounds__(256) void lstm_seq_k(
    int hbase,
    const float* __restrict__ Wih, const float* __restrict__ Whh,
    const float* __restrict__ bih, const float* __restrict__ bhh,
    const float* __restrict__ outW, const float* __restrict__ outb,
    float* __restrict__ outBuf)
{
    extern __shared__ float smf[];
    float* Bsw = smf;                    // [768][64]  weight tile
    float* Asb = smf + 768 * 64;         // [2][32][36] A double buffer
    float* gb  = Asb + 2304;             // [64] pre-added bias
    float* Pw  = gb + 64;                // [512][8] proj weights (PROJ)
    float* ob  = Pw + 4096;              // [8]      proj bias    (PROJ)
    float (*Gs)[68] = (float(*)[68])Asb; // gates staging (reuses A buffers)

    const int tid = threadIdx.x;
    const int bx = blockIdx.x, by = blockIdx.y;
    const int n0 = bx * 16, m0 = by * 32;
    const int tx = tid & 15, ty = tid >> 4;   // 4 cols x 2 rows per thread

    // ---- one-time fills ----
    for (int e = tid * 4; e < 768 * 64; e += 1024) {
        int col = e / 768, k = e % 768;
        int jr = (col >> 4) * HSZ + n0 + (col & 15);
        float4 w = (k < 256) ? *(const float4*)(Wih + (size_t)jr * 256 + k)
                             : *(const float4*)(Whh + (size_t)jr * HSZ + (k - 256));
        Bsw[(k + 0) * 64 + col] = w.x;
        Bsw[(k + 1) * 64 + col] = w.y;
        Bsw[(k + 2) * 64 + col] = w.z;
        Bsw[(k + 3) * 64 + col] = w.w;
    }
    if (tid < 64)
        gb[tid] = bih[(tid >> 4) * HSZ + n0 + (tid & 15)]
                + bhh[(tid >> 4) * HSZ + n0 + (tid & 15)];
    if constexpr (PROJ) {
        for (int e = tid; e < 4096; e += 256) {
            int q = e >> 9, k = e & 511;
            Pw[k * 8 + q] = outW[(size_t)(bx * 8 + q) * HSZ + k];
        }
        if (tid < 8) ob[tid] = outb[bx * 8 + tid];
    }
    __syncthreads();

    float ra[4];
    auto LOADA = [&](int kb, int t, const float* hin) {
        const int kbase = kb * 32;
#pragma unroll
        for (int j = 0; j < 4; j++) {
            int e = tid + j * 256;
            int row = e >> 5, kk = e & 31, k = kbase + kk;
            ra[j] = (k < 256)
                ? g_X[((size_t)(m0 + row) * LL + t) * 256 + k]
                : __ldcg(hin + (m0 + row) * HSZ + (k - 256));
        }
    };
    auto STOREA = [&](int pb) {
#pragma unroll
        for (int j = 0; j < 4; j++) {
            int e = tid + j * 256;
            Asb[pb * 1152 + (e >> 5) * 36 + (e & 31)] = ra[j];
        }
    };

    int ls = 0;
    LOADA(0, PROJ ? (LL - 1) : 0, g_h[hbase]);   // kb0 is pure-x
    for (int s = 0; s < LL; s++) {
        const int t = PROJ ? (LL - 1 - s) : s;
        const float* hin = g_h[(hbase + s) % 3];
        float* hout      = g_h[(hbase + s + 1) % 3];

        STOREA(0);
        ull acc2[2][2];
        acc2[0][0] = 0ull; acc2[0][1] = 0ull;
        acc2[1][0] = 0ull; acc2[1][1] = 0ull;
        float pa = 0.f;
        int p = 0;

        for (int kb = 0; kb < 24; kb++) {
            __syncthreads();
            if (kb < 23) LOADA(kb + 1, t, hin);

            if (PROJ && kb >= 8) {
                const int prow = tid >> 3, q = tid & 7;
                const float* Pk = Pw + (kb - 8) * 256;
                const float* Ar = Asb + p * 1152;
#pragma unroll 8
                for (int kk = 0; kk < 32; kk++)
                    pa = fmaf(Ar[prow * 36 + kk], Pk[kk * 8 + q], pa);
            }
            {
                const float* Ar = Asb + p * 1152;
                const float* Br = Bsw + (size_t)kb * 32 * 64 + tx * 4;
#pragma unroll
                for (int k4 = 0; k4 < 32; k4 += 4) {
                    float4 av0 = *(const float4*)(Ar + (ty * 2 + 0) * 36 + k4);
                    float4 av1 = *(const float4*)(Ar + (ty * 2 + 1) * 36 + k4);
#pragma unroll
                    for (int u = 0; u < 4; u++) {
                        ulonglong2 bv = *(const ulonglong2*)(Br + (size_t)(k4 + u) * 64);
#define FMA2R(AV, R) {                                                          \
    float a_ = (u == 0 ? (AV).x : u == 1 ? (AV).y : u == 2 ? (AV).z : (AV).w);  \
    ull pa_;                                                                    \
    asm("mov.b64 %0, {%1, %1};" : "=l"(pa_) : "f"(a_));                         \
    asm("fma.rn.f32x2 %0, %1, %2, %0;" : "+l"(acc2[R][0]) : "l"(pa_), "l"(bv.x)); \
    asm("fma.rn.f32x2 %0, %1, %2, %0;" : "+l"(acc2[R][1]) : "l"(pa_), "l"(bv.y)); }
                        FMA2R(av0, 0); FMA2R(av1, 1);
#undef FMA2R
                    }
                }
            }
            if (kb < 23) STOREA(p ^ 1);
            p ^= 1;
        }

        // stage gates (reuses A smem) and apply the cell
        __syncthreads();
#pragma unroll
        for (int r = 0; r < 2; r++) {
            float lo0, hi0, lo1, hi1;
            asm("mov.b64 {%0, %1}, %2;" : "=f"(lo0), "=f"(hi0) : "l"(acc2[r][0]));
            asm("mov.b64 {%0, %1}, %2;" : "=f"(lo1), "=f"(hi1) : "l"(acc2[r][1]));
            Gs[ty * 2 + r][tx * 4 + 0] = lo0;
            Gs[ty * 2 + r][tx * 4 + 1] = hi0;
            Gs[ty * 2 + r][tx * 4 + 2] = lo1;
            Gs[ty * 2 + r][tx * 4 + 3] = hi1;
        }
        __syncthreads();

#pragma unroll
        for (int rr = 0; rr < 2; rr++) {
            int e = tid + rr * 256;
            int row = e >> 4, nn = e & 15;
            int j = n0 + nn;
            float gi = Gs[row][nn]      + gb[nn];
            float gf = Gs[row][16 + nn] + gb[16 + nn];
            float gg = Gs[row][32 + nn] + gb[32 + nn];
            float go = Gs[row][48 + nn] + gb[48 + nn];
            float iv = 1.f / (1.f + expf(-gi));
            float fv = 1.f / (1.f + expf(-gf));
            float gv = tanhf(gg);
            float ov = 1.f / (1.f + expf(-go));
            int ci = (m0 + row) * HSZ + j;
            float cn = fv * g_c[ci] + iv * gv;
            g_c[ci] = cn;
            hout[ci] = ov * tanhf(cn);
        }

        if constexpr (PROJ) {
            const int prow = tid >> 3, q = tid & 7;
            outBuf[((size_t)(m0 + prow) * LL + t) * 256 + bx * 8 + q] = pa + ob[q];
        }

        // ---- per-row-group grid barrier (32 CTAs sharing by) ----
        __threadfence();
        __syncthreads();
        bool last = false;
        if (tid == 0) last = (atomicAdd(&g_bar_cnt[by], 1) == 31);
        if (tid == 0 && last) {
            g_bar_cnt[by] = 0;
            __threadfence();
            atomicExch(&g_bar_sen[by], ls ^ 1);
        }
        if (s < LL - 1) LOADA(0, PROJ ? (LL - 2 - s) : (s + 1), hin);  // pure x
        if (tid == 0 && !last) {
            while (*((volatile int*)&g_bar_sen[by]) != (ls ^ 1)) __nanosleep(32);
        }
        __syncthreads();
        ls ^= 1;
    }
}

// ---------------------------------------------------------------------------
extern "C" void kernel_launch(void* const* d_in, const int* in_sizes, int n_in,
                              void* d_out, int out_size) {
    const float* xin     = (const float*)d_in[0];
    const float* conv1_w = (const float*)d_in[1];
    const float* bn1_g   = (const float*)d_in[2];
    const float* bn1_b   = (const float*)d_in[3];
    const float* conv2_w = (const float*)d_in[4];
    const float* bn2_g   = (const float*)d_in[5];
    const float* bn2_b   = (const float*)d_in[6];
    const float* conv3_w = (const float*)d_in[7];
    const float* bn3_g   = (const float*)d_in[8];
    const float* bn3_b   = (const float*)d_in[9];
    const float* eWih0   = (const float*)d_in[10];
    const float* eWhh0   = (const float*)d_in[11];
    const float* ebih0   = (const float*)d_in[12];
    const float* ebhh0   = (const float*)d_in[13];
    // d_in[14..17] encoder layer-1: provably dead (never reaches the output)
    const float* dWih0   = (const float*)d_in[18];
    const float* dWhh0   = (const float*)d_in[19];
    const float* dbih0   = (const float*)d_in[20];
    const float* dbhh0   = (const float*)d_in[21];
    // d_in[22..25] decoder layer-1: provably dead
    const float* outW    = (const float*)d_in[26];
    const float* outb    = (const float*)d_in[27];
    float* out = (float*)d_out;

    void *pt0 = 0, *pa = 0;
    cudaGetSymbolAddress(&pt0, g_t0);
    cudaGetSymbolAddress(&pa,  g_a);

    const int ENC_SM = (768 * 64 + 2304 + 64) * 4;              // 206,080 B
    const int DEC_SM = (768 * 64 + 2304 + 64 + 4096 + 8) * 4;   // 222,496 B
    cudaFuncSetAttribute(lstm_seq_k<false>, cudaFuncAttributeMaxDynamicSharedMemorySize, ENC_SM);
    cudaFuncSetAttribute(lstm_seq_k<true>,  cudaFuncAttributeMaxDynamicSharedMemorySize, DEC_SM);

    zero_state_k<<<(BB * HSZ + 255) / 256, 256>>>();
    transpose_in_k<<<(BB * LL * 32 + 255) / 256, 256>>>(xin);

    // conv1: 32 -> 32
    conv1d_k<32><<<dim3(4, BB, 4), 128>>>((const float*)pt0, conv1_w, 32);
    bn_stats_k<<<32, 256>>>(bn1_g, bn1_b, 32);
    bn_apply_k<<<(int)(((size_t)BB * 32 * LL + 255) / 256), 256>>>((float*)pa, 32, 0);

    // conv2: 32 -> 64
    conv1d_k<32><<<dim3(4, BB, 8), 128>>>((const float*)pa, conv2_w, 64);
    bn_stats_k<<<64, 256>>>(bn2_g, bn2_b, 64);
    bn_apply_k<<<(int)(((size_t)BB * 64 * LL + 255) / 256), 256>>>((float*)pa, 64, 0);

    // conv3: 64 -> 256 (+ transpose to [B,L,256])
    conv1d_k<64><<<dim3(4, BB, 32), 128>>>((const float*)pa, conv3_w, 256);
    bn_stats_k<<<256, 256>>>(bn3_g, bn3_b, 256);
    bn_apply_k<<<(int)(((size_t)BB * 256 * LL + 255) / 256), 256>>>(nullptr, 256, 1);

    // encoder: 1024 steps in one persistent kernel. h starts in g_h[0].
    lstm_seq_k<false><<<dim3(32, 4), 256, ENC_SM>>>(0, eWih0, eWhh0, ebih0, ebhh0,
                                                    nullptr, nullptr, nullptr);
    // after 1024 steps, h lives in g_h[1024 % 3] = g_h[1]
    lstm_seq_k<true><<<dim3(32, 4), 256, DEC_SM>>>(1, dWih0, dWhh0, dbih0, dbhh0,
                                                   outW, outb, out);
}

// round 11
// speedup vs baseline: 1.0166x; 1.0166x over previous
#include <cuda_runtime.h>
#include <math.h>

#define BB   128
#define LL   1024
#define HSZ  512

typedef unsigned long long ull;

__device__ float g_t0[(size_t)BB * 32 * LL];      // [B,32,L] transposed input
__device__ float g_y [(size_t)BB * 256 * LL];     // conv raw out (<=256 ch)
__device__ float g_a [(size_t)BB * 64  * LL];     // activated conv (<=64 ch)
__device__ float g_X [(size_t)BB * LL * 256];     // conv stack out [B,L,256]
__device__ float g_scale[256];
__device__ float g_shift[256];
__device__ float g_h[3][BB * HSZ];                // 3-buffer rotation
__device__ float g_c[BB * HSZ];
__device__ int   g_bar_cnt[4];                    // per row-group barriers
__device__ int   g_bar_sen[4];

__global__ void zero_state_k() {
    int i = blockIdx.x * 256 + threadIdx.x;
    if (i < BB * HSZ) { g_h[0][i] = 0.f; g_c[i] = 0.f; }
    if (i < 4) { g_bar_cnt[i] = 0; g_bar_sen[i] = 0; }
}

__global__ void transpose_in_k(const float* __restrict__ xin) {
    int idx = blockIdx.x * 256 + threadIdx.x;      // B*L*32, c fastest
    if (idx >= BB * LL * 32) return;
    int c = idx & 31;
    int bl = idx >> 5;
    int l = bl & (LL - 1);
    int b = bl >> 10;
    g_t0[((size_t)b * 32 + c) * LL + l] = xin[idx];
}

// conv1d K=7 pad=3 stride=1, [B,C,L]. grid(L/256, B, Cout/8), 128 thr.
template<int CIN>
__global__ __launch_bounds__(128) void conv1d_k(const float* __restrict__ in,
                                                const float* __restrict__ w,
                                                int Cout) {
    const int l0 = blockIdx.x * 256, b = blockIdx.y, co0 = blockIdx.z * 8;
    __shared__ float xs[32][264];
    __shared__ float ws[8][32][8];
    float acc[8][2];
#pragma unroll
    for (int i = 0; i < 8; i++) { acc[i][0] = 0.f; acc[i][1] = 0.f; }

    for (int cb = 0; cb < CIN; cb += 32) {
        __syncthreads();
        for (int e = threadIdx.x; e < 32 * 262; e += 128) {
            int ci = e / 262, jj = e - ci * 262;
            int l = l0 - 3 + jj;
            xs[ci][jj] = (l >= 0 && l < LL) ? in[((size_t)b * CIN + cb + ci) * LL + l] : 0.f;
        }
        for (int e = threadIdx.x; e < 8 * 32 * 7; e += 128) {
            int co = e / 224, r = e - co * 224;
            int ci = r / 7, k = r - ci * 7;
            ws[co][ci][k] = w[((size_t)(co0 + co) * CIN + cb + ci) * 7 + k];
        }
        __syncthreads();
        const int lt = threadIdx.x;
        for (int ci = 0; ci < 32; ci++) {
#pragma unroll
            for (int k = 0; k < 7; k++) {
                float x0 = xs[ci][lt + k];
                float x1 = xs[ci][lt + 128 + k];
#pragma unroll
                for (int co = 0; co < 8; co++) {
                    float wv = ws[co][ci][k];
                    acc[co][0] = fmaf(x0, wv, acc[co][0]);
                    acc[co][1] = fmaf(x1, wv, acc[co][1]);
                }
            }
        }
    }
#pragma unroll
    for (int co = 0; co < 8; co++) {
        g_y[((size_t)b * Cout + co0 + co) * LL + l0 + threadIdx.x]       = acc[co][0];
        g_y[((size_t)b * Cout + co0 + co) * LL + l0 + 128 + threadIdx.x] = acc[co][1];
    }
}

__global__ void bn_stats_k(const float* __restrict__ gam,
                           const float* __restrict__ bet, int C) {
    int c = blockIdx.x;
    float s = 0.f, s2 = 0.f;
    for (int i = threadIdx.x; i < BB * LL; i += 256) {
        float v = g_y[((size_t)(i >> 10) * C + c) * LL + (i & (LL - 1))];
        s += v; s2 += v * v;
    }
    __shared__ float rs[256], rq[256];
    rs[threadIdx.x] = s; rq[threadIdx.x] = s2;
    __syncthreads();
    for (int o = 128; o > 0; o >>= 1) {
        if (threadIdx.x < o) { rs[threadIdx.x] += rs[threadIdx.x + o]; rq[threadIdx.x] += rq[threadIdx.x + o]; }
        __syncthreads();
    }
    if (threadIdx.x == 0) {
        float inv = 1.f / (float)(BB * LL);
        float mean = rs[0] * inv;
        float var  = rq[0] * inv - mean * mean;
        float sc = gam[c] * rsqrtf(var + 1e-5f);
        g_scale[c] = sc;
        g_shift[c] = bet[c] - mean * sc;
    }
}

__global__ void bn_apply_k(float* __restrict__ outBCL, int C, int toBLC) {
    size_t idx = (size_t)blockIdx.x * 256 + threadIdx.x;
    if (idx >= (size_t)BB * C * LL) return;
    int l = (int)(idx & (LL - 1));
    size_t bc = idx >> 10;
    int c = (int)(bc % C);
    int b = (int)(bc / C);
    float v = fmaxf(g_y[idx] * g_scale[c] + g_shift[c], 0.f);
    if (toBLC) g_X[((size_t)b * LL + l) * 256 + c] = v;
    else       outBCL[idx] = v;
}

// ---------------------------------------------------------------------------
// Persistent LSTM sequence kernel. grid (32,4) = 128 CTAs, 256 threads (8 w).
// CTA tile: 32 rows x 64 gate cols, K=768 in 24 chunks of 32.
// Weights SMEM-resident for all 1024 steps; FFMA2 inner product; per-row-group
// (by) grid barrier each step; x-chunk prefetched under the barrier.
// ---------------------------------------------------------------------------
template<bool PROJ>
__global__ __launch_bounds__(256) void lstm_seq_k(
    int hbase,
    const float* __restrict__ Wih, const float* __restrict__ Whh,
    const float* __restrict__ bih, const float* __restrict__ bhh,
    const float* __restrict__ outW, const float* __restrict__ outb,
    float* __restrict__ outBuf)
{
    extern __shared__ float smf[];
    float* Bsw = smf;                    // [768][64]  weight tile
    float* Asb = smf + 768 * 64;         // [2][32][36] A double buffer
    float* gb  = Asb + 2304;             // [64] pre-added bias
    float* Pw  = gb + 64;                // [512][8] proj weights (PROJ)
    float* ob  = Pw + 4096;              // [8]      proj bias    (PROJ)
    float (*Gs)[68] = (float(*)[68])Asb; // gates staging (reuses A buffers)

    const int tid = threadIdx.x;
    const int bx = blockIdx.x, by = blockIdx.y;
    const int n0 = bx * 16, m0 = by * 32;
    const int tx = tid & 15, ty = tid >> 4;   // 4 cols x 2 rows per thread

    // ---- one-time fills ----
    for (int e = tid * 4; e < 768 * 64; e += 1024) {
        int col = e / 768, k = e % 768;
        int jr = (col >> 4) * HSZ + n0 + (col & 15);
        float4 w = (k < 256) ? *(const float4*)(Wih + (size_t)jr * 256 + k)
                             : *(const float4*)(Whh + (size_t)jr * HSZ + (k - 256));
        Bsw[(k + 0) * 64 + col] = w.x;
        Bsw[(k + 1) * 64 + col] = w.y;
        Bsw[(k + 2) * 64 + col] = w.z;
        Bsw[(k + 3) * 64 + col] = w.w;
    }
    if (tid < 64)
        gb[tid] = bih[(tid >> 4) * HSZ + n0 + (tid & 15)]
                + bhh[(tid >> 4) * HSZ + n0 + (tid & 15)];
    if constexpr (PROJ) {
        for (int e = tid; e < 4096; e += 256) {
            int q = e >> 9, k = e & 511;
            Pw[k * 8 + q] = outW[(size_t)(bx * 8 + q) * HSZ + k];
        }
        if (tid < 8) ob[tid] = outb[bx * 8 + tid];
    }
    __syncthreads();

    float ra[4];
    auto LOADA = [&](int kb, int t, const float* hin) {
        const int kbase = kb * 32;
#pragma unroll
        for (int j = 0; j < 4; j++) {
            int e = tid + j * 256;
            int row = e >> 5, kk = e & 31, k = kbase + kk;
            ra[j] = (k < 256)
                ? g_X[((size_t)(m0 + row) * LL + t) * 256 + k]
                : __ldcg(hin + (m0 + row) * HSZ + (k - 256));
        }
    };
    auto STOREA = [&](int pb) {
#pragma unroll
        for (int j = 0; j < 4; j++) {
            int e = tid + j * 256;
            Asb[pb * 1152 + (e >> 5) * 36 + (e & 31)] = ra[j];
        }
    };

    int ls = 0;
    LOADA(0, PROJ ? (LL - 1) : 0, g_h[hbase]);   // kb0 is pure-x
    for (int s = 0; s < LL; s++) {
        const int t = PROJ ? (LL - 1 - s) : s;
        const float* hin = g_h[(hbase + s) % 3];
        float* hout      = g_h[(hbase + s + 1) % 3];

        STOREA(0);
        ull acc2[2][2];
        acc2[0][0] = 0ull; acc2[0][1] = 0ull;
        acc2[1][0] = 0ull; acc2[1][1] = 0ull;
        float pa = 0.f;
        int p = 0;

        for (int kb = 0; kb < 24; kb++) {
            __syncthreads();
            if (kb < 23) LOADA(kb + 1, t, hin);

            if (PROJ && kb >= 8) {
                const int prow = tid >> 3, q = tid & 7;
                const float* Pk = Pw + (kb - 8) * 256;
                const float* Ar = Asb + p * 1152;
#pragma unroll 8
                for (int kk = 0; kk < 32; kk++)
                    pa = fmaf(Ar[prow * 36 + kk], Pk[kk * 8 + q], pa);
            }
            {
                const float* Ar = Asb + p * 1152;
                const float* Br = Bsw + (size_t)kb * 32 * 64 + tx * 4;
#pragma unroll
                for (int k4 = 0; k4 < 32; k4 += 4) {
                    float4 av0 = *(const float4*)(Ar + (ty * 2 + 0) * 36 + k4);
                    float4 av1 = *(const float4*)(Ar + (ty * 2 + 1) * 36 + k4);
#pragma unroll
                    for (int u = 0; u < 4; u++) {
                        ulonglong2 bv = *(const ulonglong2*)(Br + (size_t)(k4 + u) * 64);
#define FMA2R(AV, R) {                                                          \
    float a_ = (u == 0 ? (AV).x : u == 1 ? (AV).y : u == 2 ? (AV).z : (AV).w);  \
    ull pa_;                                                                    \
    asm("mov.b64 %0, {%1, %1};" : "=l"(pa_) : "f"(a_));                         \
    asm("fma.rn.f32x2 %0, %1, %2, %0;" : "+l"(acc2[R][0]) : "l"(pa_), "l"(bv.x)); \
    asm("fma.rn.f32x2 %0, %1, %2, %0;" : "+l"(acc2[R][1]) : "l"(pa_), "l"(bv.y)); }
                        FMA2R(av0, 0); FMA2R(av1, 1);
#undef FMA2R
                    }
                }
            }
            if (kb < 23) STOREA(p ^ 1);
            p ^= 1;
        }

        // stage gates (reuses A smem) and apply the cell
        __syncthreads();
#pragma unroll
        for (int r = 0; r < 2; r++) {
            float lo0, hi0, lo1, hi1;
            asm("mov.b64 {%0, %1}, %2;" : "=f"(lo0), "=f"(hi0) : "l"(acc2[r][0]));
            asm("mov.b64 {%0, %1}, %2;" : "=f"(lo1), "=f"(hi1) : "l"(acc2[r][1]));
            Gs[ty * 2 + r][tx * 4 + 0] = lo0;
            Gs[ty * 2 + r][tx * 4 + 1] = hi0;
            Gs[ty * 2 + r][tx * 4 + 2] = lo1;
            Gs[ty * 2 + r][tx * 4 + 3] = hi1;
        }
        __syncthreads();

#pragma unroll
        for (int rr = 0; rr < 2; rr++) {
            int e = tid + rr * 256;
            int row = e >> 4, nn = e & 15;
            int j = n0 + nn;
            float gi = Gs[row][nn]      + gb[nn];
            float gf = Gs[row][16 + nn] + gb[16 + nn];
            float gg = Gs[row][32 + nn] + gb[32 + nn];
            float go = Gs[row][48 + nn] + gb[48 + nn];
            float iv = 1.f / (1.f + expf(-gi));
            float fv = 1.f / (1.f + expf(-gf));
            float gv = tanhf(gg);
            float ov = 1.f / (1.f + expf(-go));
            int ci = (m0 + row) * HSZ + j;
            float cn = fv * g_c[ci] + iv * gv;
            g_c[ci] = cn;
            hout[ci] = ov * tanhf(cn);
        }

        if constexpr (PROJ) {
            const int prow = tid >> 3, q = tid & 7;
            outBuf[((size_t)(m0 + prow) * LL + t) * 256 + bx * 8 + q] = pa + ob[q];
        }

        // ---- per-row-group grid barrier (32 CTAs sharing by) ----
        __threadfence();
        __syncthreads();
        bool last = false;
        if (tid == 0) last = (atomicAdd(&g_bar_cnt[by], 1) == 31);
        if (tid == 0 && last) {
            g_bar_cnt[by] = 0;
            __threadfence();
            atomicExch(&g_bar_sen[by], ls ^ 1);
        }
        if (s < LL - 1) LOADA(0, PROJ ? (LL - 2 - s) : (s + 1), hin);  // pure x
        if (tid == 0 && !last) {
            while (*((volatile int*)&g_bar_sen[by]) != (ls ^ 1)) __nanosleep(32);
        }
        __syncthreads();
        ls ^= 1;
    }
}

// ---------------------------------------------------------------------------
extern "C" void kernel_launch(void* const* d_in, const int* in_sizes, int n_in,
                              void* d_out, int out_size) {
    const float* xin     = (const float*)d_in[0];
    const float* conv1_w = (const float*)d_in[1];
    const float* bn1_g   = (const float*)d_in[2];
    const float* bn1_b   = (const float*)d_in[3];
    const float* conv2_w = (const float*)d_in[4];
    const float* bn2_g   = (const float*)d_in[5];
    const float* bn2_b   = (const float*)d_in[6];
    const float* conv3_w = (const float*)d_in[7];
    const float* bn3_g   = (const float*)d_in[8];
    const float* bn3_b   = (const float*)d_in[9];
    const float* eWih0   = (const float*)d_in[10];
    const float* eWhh0   = (const float*)d_in[11];
    const float* ebih0   = (const float*)d_in[12];
    const float* ebhh0   = (const float*)d_in[13];
    // d_in[14..17] encoder layer-1: provably dead (never reaches the output)
    const float* dWih0   = (const float*)d_in[18];
    const float* dWhh0   = (const float*)d_in[19];
    const float* dbih0   = (const float*)d_in[20];
    const float* dbhh0   = (const float*)d_in[21];
    // d_in[22..25] decoder layer-1: provably dead
    const float* outW    = (const float*)d_in[26];
    const float* outb    = (const float*)d_in[27];
    float* out = (float*)d_out;

    void *pt0 = 0, *pa = 0;
    cudaGetSymbolAddress(&pt0, g_t0);
    cudaGetSymbolAddress(&pa,  g_a);

    const int ENC_SM = (768 * 64 + 2304 + 64) * 4;              // 206,080 B
    const int DEC_SM = (768 * 64 + 2304 + 64 + 4096 + 8) * 4;   // 222,496 B
    cudaFuncSetAttribute(lstm_seq_k<false>, cudaFuncAttributeMaxDynamicSharedMemorySize, ENC_SM);
    cudaFuncSetAttribute(lstm_seq_k<true>,  cudaFuncAttributeMaxDynamicSharedMemorySize, DEC_SM);

    zero_state_k<<<(BB * HSZ + 255) / 256, 256>>>();
    transpose_in_k<<<(BB * LL * 32 + 255) / 256, 256>>>(xin);

    // conv1: 32 -> 32
    conv1d_k<32><<<dim3(4, BB, 4), 128>>>((const float*)pt0, conv1_w, 32);
    bn_stats_k<<<32, 256>>>(bn1_g, bn1_b, 32);
    bn_apply_k<<<(int)(((size_t)BB * 32 * LL + 255) / 256), 256>>>((float*)pa, 32, 0);

    // conv2: 32 -> 64
    conv1d_k<32><<<dim3(4, BB, 8), 128>>>((const float*)pa, conv2_w, 64);
    bn_stats_k<<<64, 256>>>(bn2_g, bn2_b, 64);
    bn_apply_k<<<(int)(((size_t)BB * 64 * LL + 255) / 256), 256>>>((float*)pa, 64, 0);

    // conv3: 64 -> 256 (+ transpose to [B,L,256])
    conv1d_k<64><<<dim3(4, BB, 32), 128>>>((const float*)pa, conv3_w, 256);
    bn_stats_k<<<256, 256>>>(bn3_g, bn3_b, 256);
    bn_apply_k<<<(int)(((size_t)BB * 256 * LL + 255) / 256), 256>>>(nullptr, 256, 1);

    // encoder: 1024 steps in one persistent kernel. h starts in g_h[0].
    lstm_seq_k<false><<<dim3(32, 4), 256, ENC_SM>>>(0, eWih0, eWhh0, ebih0, ebhh0,
                                                    nullptr, nullptr, nullptr);
    // after 1024 steps, h lives in g_h[1024 % 3] = g_h[1]
    lstm_seq_k<true><<<dim3(32, 4), 256, DEC_SM>>>(1, dWih0, dWhh0, dbih0, dbhh0,
                                                   outW, outb, out);
}

// round 12
// speedup vs baseline: 1.2584x; 1.2379x over previous
#include <cuda_runtime.h>
#include <math.h>

#define BB   128
#define LL   1024
#define HSZ  512

typedef unsigned long long ull;

// ---------------- static scratch ----------------
__device__ float g_t0[(size_t)BB * 32 * LL];      // [B,32,L] transposed input
__device__ float g_a [(size_t)BB * 64  * LL];     // conv1 raw out (32ch used)
__device__ float g_y [(size_t)BB * 256 * LL];     // conv2 raw out (64ch used)
__device__ float g_z [(size_t)BB * 256 * LL];     // conv3 raw out (256ch)
__device__ float g_X [(size_t)BB * LL * 256];     // conv stack out [B,L,256]
__device__ float g_h[3][BB * HSZ];                // 3-buffer h rotation
__device__ float g_c[BB * HSZ];
__device__ int   g_bar_cnt[4];
__device__ int   g_bar_sen[4];
__device__ float g_s1[32],  g_q1[32];             // BN batch-stat accumulators
__device__ float g_s2[64],  g_q2[64];
__device__ float g_s3[256], g_q3[256];

// ---------------- P0: zero state/stats + transpose ----------------
__global__ void prep0_k(const float* __restrict__ xin) {
    int idx = blockIdx.x * 256 + threadIdx.x;
    if (idx < BB * HSZ) { g_h[0][idx] = 0.f; g_c[idx] = 0.f; }
    if (idx < 4)   { g_bar_cnt[idx] = 0; g_bar_sen[idx] = 0; }
    if (idx < 32)  { g_s1[idx] = 0.f; g_q1[idx] = 0.f; }
    if (idx < 64)  { g_s2[idx] = 0.f; g_q2[idx] = 0.f; }
    if (idx < 256) { g_s3[idx] = 0.f; g_q3[idx] = 0.f; }
    if (idx < BB * LL * 32) {
        int c = idx & 31;
        int bl = idx >> 5;
        int l = bl & (LL - 1);
        int b = bl >> 10;
        g_t0[((size_t)b * 32 + c) * LL + l] = xin[idx];
    }
}

// ---------------- fused conv1d (K=7,pad3) + input-BN + output-stats --------
// grid(L/256, B, Cout/8), 128 thr. If BNIN: input is RAW prev-conv output;
// apply scale/shift (from accumulated batch stats) + ReLU on load.
// Always: accumulate this conv's raw-output sum/sumsq via block-reduce+atomics.
template<int CIN, bool BNIN>
__global__ __launch_bounds__(128) void conv_bn_k(
    const float* __restrict__ in, const float* __restrict__ w, int Cout,
    float* __restrict__ out,
    const float* __restrict__ sumIn, const float* __restrict__ sqIn,
    const float* __restrict__ gamIn, const float* __restrict__ betIn,
    float* __restrict__ sumOut, float* __restrict__ sqOut)
{
    const int l0 = blockIdx.x * 256, b = blockIdx.y, co0 = blockIdx.z * 8;
    __shared__ float xs[32][264];
    __shared__ float ws[8][32][8];
    __shared__ float sc[64], sh[64];
    __shared__ float wred_s[4][8], wred_q[4][8];
    const int tid = threadIdx.x;

    if (BNIN && tid < CIN) {
        float inv = 1.f / (float)(BB * LL);
        float mean = sumIn[tid] * inv;
        float var  = sqIn[tid] * inv - mean * mean;
        float s = gamIn[tid] * rsqrtf(var + 1e-5f);
        sc[tid] = s;
        sh[tid] = betIn[tid] - mean * s;
    }
    if (BNIN) __syncthreads();

    float acc[8][2];
#pragma unroll
    for (int i = 0; i < 8; i++) { acc[i][0] = 0.f; acc[i][1] = 0.f; }

    for (int cb = 0; cb < CIN; cb += 32) {
        __syncthreads();
        for (int e = tid; e < 32 * 262; e += 128) {
            int ci = e / 262, jj = e - ci * 262;
            int l = l0 - 3 + jj;
            float v = 0.f;
            if (l >= 0 && l < LL) {
                v = in[((size_t)b * CIN + cb + ci) * LL + l];
                if (BNIN) v = fmaxf(v * sc[cb + ci] + sh[cb + ci], 0.f);
            }
            xs[ci][jj] = v;
        }
        for (int e = tid; e < 8 * 32 * 7; e += 128) {
            int co = e / 224, r = e - co * 224;
            int ci = r / 7, k = r - ci * 7;
            ws[co][ci][k] = w[((size_t)(co0 + co) * CIN + cb + ci) * 7 + k];
        }
        __syncthreads();
        for (int ci = 0; ci < 32; ci++) {
#pragma unroll
            for (int k = 0; k < 7; k++) {
                float x0 = xs[ci][tid + k];
                float x1 = xs[ci][tid + 128 + k];
#pragma unroll
                for (int co = 0; co < 8; co++) {
                    float wv = ws[co][ci][k];
                    acc[co][0] = fmaf(x0, wv, acc[co][0]);
                    acc[co][1] = fmaf(x1, wv, acc[co][1]);
                }
            }
        }
    }
#pragma unroll
    for (int co = 0; co < 8; co++) {
        out[((size_t)b * Cout + co0 + co) * LL + l0 + tid]       = acc[co][0];
        out[((size_t)b * Cout + co0 + co) * LL + l0 + 128 + tid] = acc[co][1];
    }

    // raw-output batch stats: block reduce, one atomic per channel
    const int lane = tid & 31, wid = tid >> 5;
#pragma unroll
    for (int co = 0; co < 8; co++) {
        float s = acc[co][0] + acc[co][1];
        float q = acc[co][0] * acc[co][0] + acc[co][1] * acc[co][1];
#pragma unroll
        for (int o = 16; o > 0; o >>= 1) {
            s += __shfl_down_sync(0xFFFFFFFFu, s, o);
            q += __shfl_down_sync(0xFFFFFFFFu, q, o);
        }
        if (lane == 0) { wred_s[wid][co] = s; wred_q[wid][co] = q; }
    }
    __syncthreads();
    if (tid < 8) {
        float S = 0.f, Q = 0.f;
#pragma unroll
        for (int ww = 0; ww < 4; ww++) { S += wred_s[ww][tid]; Q += wred_q[ww][tid]; }
        atomicAdd(&sumOut[co0 + tid], S);
        atomicAdd(&sqOut[co0 + tid], Q);
    }
}

// ---------------- P4: finalize BN3 + ReLU + transpose -> g_X ----------------
__global__ void bn3_to_X_k(const float* __restrict__ gam, const float* __restrict__ bet) {
    size_t idx = (size_t)blockIdx.x * 256 + threadIdx.x;
    if (idx >= (size_t)BB * 256 * LL) return;
    int l = (int)(idx & (LL - 1));
    size_t bc = idx >> 10;
    int c = (int)(bc % 256);
    int b = (int)(bc / 256);
    float inv = 1.f / (float)(BB * LL);
    float mean = g_s3[c] * inv;
    float var  = g_q3[c] * inv - mean * mean;
    float s = gam[c] * rsqrtf(var + 1e-5f);
    float v = fmaxf(g_z[idx] * s + (bet[c] - mean * s), 0.f);
    g_X[((size_t)b * LL + l) * 256 + c] = v;
}

// ---------------------------------------------------------------------------
// Persistent LSTM sequence kernel. grid (38,4)=152 CTAs (bx>=32 exit at once:
// grid>=148 dodges the documented low-grid SM-issue throttle; workers occupy
// bids <=145 so worker co-residency is guaranteed). 128 threads.
// CTA tile: 32 rows x 64 gate cols. K=768 in 12 chunks of 64 (double-buffered
// SMEM A; weights SMEM-resident for all 1024 steps). FFMA2 inner product.
// Per-row-group (by) grid barrier each step; next x-chunk prefetched under it.
// ---------------------------------------------------------------------------
template<bool PROJ>
__global__ __launch_bounds__(128) void lstm_seq_k(
    int hbase,
    const float* __restrict__ Wih, const float* __restrict__ Whh,
    const float* __restrict__ bih, const float* __restrict__ bhh,
    const float* __restrict__ outW, const float* __restrict__ outb,
    float* __restrict__ outBuf)
{
    if (blockIdx.x >= 32) return;   // dummy CTAs (grid padding to 152)

    extern __shared__ float smf[];
    float* Bsw = smf;                    // [768][64]  weight tile (192KB)
    float* Asb = smf + 768 * 64;         // [2][32][68] A double buffer
    float* gb  = Asb + 2 * 2176;         // [64] pre-added bias
    float* Pw  = gb + 64;                // [512][8] proj weights (PROJ)
    float* ob  = Pw + 4096;              // [8]      proj bias    (PROJ)
    float (*Gs)[68] = (float(*)[68])Asb; // gates staging (reuses A buffers)

    const int tid = threadIdx.x;
    const int bx = blockIdx.x, by = blockIdx.y;
    const int n0 = bx * 16, m0 = by * 32;
    const int tx = tid & 15, ty = tid >> 4;   // 4 cols x 4 rows per thread

    // ---- one-time fills ----
    for (int e = tid * 4; e < 768 * 64; e += 512) {
        int col = e / 768, k = e % 768;
        int jr = (col >> 4) * HSZ + n0 + (col & 15);
        float4 w = (k < 256) ? *(const float4*)(Wih + (size_t)jr * 256 + k)
                             : *(const float4*)(Whh + (size_t)jr * HSZ + (k - 256));
        Bsw[(k + 0) * 64 + col] = w.x;
        Bsw[(k + 1) * 64 + col] = w.y;
        Bsw[(k + 2) * 64 + col] = w.z;
        Bsw[(k + 3) * 64 + col] = w.w;
    }
    if (tid < 64)
        gb[tid] = bih[(tid >> 4) * HSZ + n0 + (tid & 15)]
                + bhh[(tid >> 4) * HSZ + n0 + (tid & 15)];
    if constexpr (PROJ) {
        for (int e = tid; e < 4096; e += 128) {
            int q = e >> 9, k = e & 511;
            Pw[k * 8 + q] = outW[(size_t)(bx * 8 + q) * HSZ + k];
        }
        if (tid < 8) ob[tid] = outb[bx * 8 + tid];
    }
    __syncthreads();

    float ra[16];
    auto LOADA = [&](int kb, int t, const float* hin) {
        const int kbase = kb * 64;
#pragma unroll
        for (int j = 0; j < 16; j++) {
            int e = tid + j * 128;
            int row = e >> 6, kk = e & 63, k = kbase + kk;
            ra[j] = (k < 256)
                ? g_X[((size_t)(m0 + row) * LL + t) * 256 + k]
                : __ldcg(hin + (m0 + row) * HSZ + (k - 256));
        }
    };
    auto STOREA = [&](int pb) {
#pragma unroll
        for (int j = 0; j < 16; j++) {
            int e = tid + j * 128;
            Asb[pb * 2176 + (e >> 6) * 68 + (e & 63)] = ra[j];
        }
    };

    int ls = 0;
    LOADA(0, PROJ ? (LL - 1) : 0, g_h[hbase]);   // chunk 0 is pure-x
    for (int s = 0; s < LL; s++) {
        const int t = PROJ ? (LL - 1 - s) : s;
        const float* hin = g_h[(hbase + s) % 3];
        float* hout      = g_h[(hbase + s + 1) % 3];

        STOREA(0);
        ull acc2[4][2];
#pragma unroll
        for (int r = 0; r < 4; r++) { acc2[r][0] = 0ull; acc2[r][1] = 0ull; }
        float pa0 = 0.f, pa1 = 0.f;
        int p = 0;

        for (int kb = 0; kb < 12; kb++) {
            __syncthreads();
            if (kb < 11) LOADA(kb + 1, t, hin);

            if (PROJ && kb >= 4) {
                const int prow = tid >> 3, q = tid & 7;
                const float* Pk = Pw + (kb - 4) * 512;
                const float* Ar = Asb + p * 2176;
#pragma unroll 8
                for (int kk = 0; kk < 64; kk++) {
                    float w0 = Pk[kk * 8 + q];
                    pa0 = fmaf(Ar[prow * 68 + kk],        w0, pa0);
                    pa1 = fmaf(Ar[(prow + 16) * 68 + kk], w0, pa1);
                }
            }
            {
                const float* Ar = Asb + p * 2176;
                const float* Br = Bsw + (size_t)kb * 4096 + tx * 4;
#pragma unroll
                for (int k4 = 0; k4 < 64; k4 += 4) {
                    float4 av0 = *(const float4*)(Ar + (ty * 4 + 0) * 68 + k4);
                    float4 av1 = *(const float4*)(Ar + (ty * 4 + 1) * 68 + k4);
                    float4 av2 = *(const float4*)(Ar + (ty * 4 + 2) * 68 + k4);
                    float4 av3 = *(const float4*)(Ar + (ty * 4 + 3) * 68 + k4);
#pragma unroll
                    for (int u = 0; u < 4; u++) {
                        ulonglong2 bv = *(const ulonglong2*)(Br + (size_t)(k4 + u) * 64);
#define FMA2R(AV, R) {                                                          \
    float a_ = (u == 0 ? (AV).x : u == 1 ? (AV).y : u == 2 ? (AV).z : (AV).w);  \
    ull pa_;                                                                    \
    asm("mov.b64 %0, {%1, %1};" : "=l"(pa_) : "f"(a_));                         \
    asm("fma.rn.f32x2 %0, %1, %2, %0;" : "+l"(acc2[R][0]) : "l"(pa_), "l"(bv.x)); \
    asm("fma.rn.f32x2 %0, %1, %2, %0;" : "+l"(acc2[R][1]) : "l"(pa_), "l"(bv.y)); }
                        FMA2R(av0, 0); FMA2R(av1, 1); FMA2R(av2, 2); FMA2R(av3, 3);
#undef FMA2R
                    }
                }
            }
            if (kb < 11) STOREA(p ^ 1);
            p ^= 1;
        }

        // stage gates (reuses A smem) and apply the cell
        __syncthreads();
#pragma unroll
        for (int r = 0; r < 4; r++) {
            float lo0, hi0, lo1, hi1;
            asm("mov.b64 {%0, %1}, %2;" : "=f"(lo0), "=f"(hi0) : "l"(acc2[r][0]));
            asm("mov.b64 {%0, %1}, %2;" : "=f"(lo1), "=f"(hi1) : "l"(acc2[r][1]));
            Gs[ty * 4 + r][tx * 4 + 0] = lo0;
            Gs[ty * 4 + r][tx * 4 + 1] = hi0;
            Gs[ty * 4 + r][tx * 4 + 2] = lo1;
            Gs[ty * 4 + r][tx * 4 + 3] = hi1;
        }
        __syncthreads();

#pragma unroll
        for (int rr = 0; rr < 4; rr++) {
            int e = tid + rr * 128;
            int row = e >> 4, nn = e & 15;
            int j = n0 + nn;
            float gi = Gs[row][nn]      + gb[nn];
            float gf = Gs[row][16 + nn] + gb[16 + nn];
            float gg = Gs[row][32 + nn] + gb[32 + nn];
            float go = Gs[row][48 + nn] + gb[48 + nn];
            float iv = 1.f / (1.f + __expf(-gi));
            float fv = 1.f / (1.f + __expf(-gf));
            float gv = tanhf(gg);
            float ov = 1.f / (1.f + __expf(-go));
            int ci = (m0 + row) * HSZ + j;
            float cn = fv * g_c[ci] + iv * gv;
            g_c[ci] = cn;
            hout[ci] = ov * tanhf(cn);
        }

        if constexpr (PROJ) {
            const int prow = tid >> 3, q = tid & 7;
            float bo = ob[q];
            outBuf[((size_t)(m0 + prow) * LL + t) * 256 + bx * 8 + q]      = pa0 + bo;
            outBuf[((size_t)(m0 + prow + 16) * LL + t) * 256 + bx * 8 + q] = pa1 + bo;
        }

        // ---- per-row-group grid barrier (32 worker CTAs share by) ----
        __threadfence();
        __syncthreads();
        bool last = false;
        if (tid == 0) last = (atomicAdd(&g_bar_cnt[by], 1) == 31);
        if (tid == 0 && last) {
            g_bar_cnt[by] = 0;
            __threadfence();
            atomicExch(&g_bar_sen[by], ls ^ 1);
        }
        if (s < LL - 1) LOADA(0, PROJ ? (LL - 2 - s) : (s + 1), hin);  // pure x
        if (tid == 0 && !last) {
            while (*((volatile int*)&g_bar_sen[by]) != (ls ^ 1)) __nanosleep(32);
        }
        __syncthreads();
        ls ^= 1;
    }
}

// ---------------------------------------------------------------------------
extern "C" void kernel_launch(void* const* d_in, const int* in_sizes, int n_in,
                              void* d_out, int out_size) {
    const float* xin     = (const float*)d_in[0];
    const float* conv1_w = (const float*)d_in[1];
    const float* bn1_g   = (const float*)d_in[2];
    const float* bn1_b   = (const float*)d_in[3];
    const float* conv2_w = (const float*)d_in[4];
    const float* bn2_g   = (const float*)d_in[5];
    const float* bn2_b   = (const float*)d_in[6];
    const float* conv3_w = (const float*)d_in[7];
    const float* bn3_g   = (const float*)d_in[8];
    const float* bn3_b   = (const float*)d_in[9];
    const float* eWih0   = (const float*)d_in[10];
    const float* eWhh0   = (const float*)d_in[11];
    const float* ebih0   = (const float*)d_in[12];
    const float* ebhh0   = (const float*)d_in[13];
    // d_in[14..17] encoder layer-1: provably dead (never reaches the output)
    const float* dWih0   = (const float*)d_in[18];
    const float* dWhh0   = (const float*)d_in[19];
    const float* dbih0   = (const float*)d_in[20];
    const float* dbhh0   = (const float*)d_in[21];
    // d_in[22..25] decoder layer-1: provably dead
    const float* outW    = (const float*)d_in[26];
    const float* outb    = (const float*)d_in[27];
    float* out = (float*)d_out;

    void *pt0 = 0, *pa = 0, *py = 0, *pz = 0;
    void *ps1 = 0, *pq1 = 0, *ps2 = 0, *pq2 = 0, *ps3 = 0, *pq3 = 0;
    cudaGetSymbolAddress(&pt0, g_t0);
    cudaGetSymbolAddress(&pa,  g_a);
    cudaGetSymbolAddress(&py,  g_y);
    cudaGetSymbolAddress(&pz,  g_z);
    cudaGetSymbolAddress(&ps1, g_s1); cudaGetSymbolAddress(&pq1, g_q1);
    cudaGetSymbolAddress(&ps2, g_s2); cudaGetSymbolAddress(&pq2, g_q2);
    cudaGetSymbolAddress(&ps3, g_s3); cudaGetSymbolAddress(&pq3, g_q3);

    const int ENC_SM = (768 * 64 + 2 * 2176 + 64) * 4;              // 214,272 B
    const int DEC_SM = (768 * 64 + 2 * 2176 + 64 + 4096 + 8) * 4;   // 230,688 B
    cudaFuncSetAttribute(lstm_seq_k<false>, cudaFuncAttributeMaxDynamicSharedMemorySize, ENC_SM);
    cudaFuncSetAttribute(lstm_seq_k<true>,  cudaFuncAttributeMaxDynamicSharedMemorySize, DEC_SM);

    // launch 0: zero state/stats + transpose input
    prep0_k<<<(BB * LL * 32 + 255) / 256, 256>>>(xin);
    // launch 1: conv1 (raw in -> raw out g_a) + stats1
    conv_bn_k<32, false><<<dim3(4, BB, 4), 128>>>(
        (const float*)pt0, conv1_w, 32, (float*)pa,
        nullptr, nullptr, nullptr, nullptr, (float*)ps1, (float*)pq1);
    // launch 2: conv2 (bn1+relu on load -> raw out g_y) + stats2
    conv_bn_k<32, true><<<dim3(4, BB, 8), 128>>>(
        (const float*)pa, conv2_w, 64, (float*)py,
        (const float*)ps1, (const float*)pq1, bn1_g, bn1_b, (float*)ps2, (float*)pq2);
    // launch 3: conv3 (bn2+relu on load -> raw out g_z) + stats3
    conv_bn_k<64, true><<<dim3(4, BB, 32), 128>>>(
        (const float*)py, conv3_w, 256, (float*)pz,
        (const float*)ps2, (const float*)pq2, bn2_g, bn2_b, (float*)ps3, (float*)pq3);
    // launch 4: finalize bn3 + relu + transpose -> g_X
    bn3_to_X_k<<<(int)(((size_t)BB * 256 * LL + 255) / 256), 256>>>(bn3_g, bn3_b);

    // launch 5: encoder (1024 steps persistent). h starts in g_h[0].
    lstm_seq_k<false><<<dim3(38, 4), 128, ENC_SM>>>(0, eWih0, eWhh0, ebih0, ebhh0,
                                                    nullptr, nullptr, nullptr);
    // launch 6: decoder. After 1024 steps h lives in g_h[1024 % 3] = g_h[1].
    lstm_seq_k<true><<<dim3(38, 4), 128, DEC_SM>>>(1, dWih0, dWhh0, dbih0, dbhh0,
                                                   outW, outb, out);
}

// round 13
// speedup vs baseline: 1.3578x; 1.0790x over previous
#include <cuda_runtime.h>
#include <math.h>

#define BB   128
#define LL   1024
#define HSZ  512
#define NCONV 592   // persistent conv grid (4 CTAs/SM x 148)

typedef unsigned long long ull;

// ---------------- static scratch ----------------
__device__ float g_t0[(size_t)BB * 32 * LL];      // [B,32,L] transposed input
__device__ float g_a [(size_t)BB * 32  * LL];     // conv1 raw out
__device__ float g_y [(size_t)BB * 64  * LL];     // conv2 raw out
__device__ float g_z [(size_t)BB * 256 * LL];     // conv3 raw out
__device__ float g_X [(size_t)BB * LL * 256];     // conv stack out [B,L,256]
__device__ float g_h[3][BB * HSZ];                // 3-buffer h rotation
__device__ float g_c[BB * HSZ];                   // c hand-off enc -> dec
__device__ int   g_bar_cnt[4];
__device__ int   g_bar_sen[4];
__device__ int   g_cbar_cnt;
__device__ int   g_cbar_sen;
__device__ float g_s1[32],  g_q1[32];             // BN batch-stat accumulators
__device__ float g_s2[64],  g_q2[64];
__device__ float g_s3[256], g_q3[256];

__device__ __forceinline__ float tanh_fast(float x) {
    return 1.f - 2.f / (__expf(2.f * x) + 1.f);
}

// ---------------- launch 0: zero state/stats/flags + transpose ----------------
__global__ void prep0_k(const float* __restrict__ xin) {
    int idx = blockIdx.x * 256 + threadIdx.x;
    if (idx < BB * HSZ) { g_h[0][idx] = 0.f; g_c[idx] = 0.f; }
    if (idx < 4)   { g_bar_cnt[idx] = 0; g_bar_sen[idx] = 0; }
    if (idx == 4)  { g_cbar_cnt = 0; g_cbar_sen = 0; }
    if (idx < 32)  { g_s1[idx] = 0.f; g_q1[idx] = 0.f; }
    if (idx < 64)  { g_s2[idx] = 0.f; g_q2[idx] = 0.f; }
    if (idx < 256) { g_s3[idx] = 0.f; g_q3[idx] = 0.f; }
    if (idx < BB * LL * 32) {
        int c = idx & 31;
        int bl = idx >> 5;
        int l = bl & (LL - 1);
        int b = bl >> 10;
        g_t0[((size_t)b * 32 + c) * LL + l] = xin[idx];
    }
}

// ---------------- conv tile body (K=7, pad 3), one 256-L x 8-co tile ----------
template<bool BNIN>
__device__ __forceinline__ void conv_tile(
    const float* __restrict__ in, const float* __restrict__ w,
    int CIN, int Cout, int l0, int b, int co0, float* __restrict__ out,
    const float* scA, const float* shA,
    float* __restrict__ sumOut, float* __restrict__ sqOut,
    float (*xs)[264], float (*ws)[32][8],
    float (*wred_s)[8], float (*wred_q)[8])
{
    const int tid = threadIdx.x;
    float acc[8][2];
#pragma unroll
    for (int i = 0; i < 8; i++) { acc[i][0] = 0.f; acc[i][1] = 0.f; }

    for (int cb = 0; cb < CIN; cb += 32) {
        __syncthreads();
        for (int e = tid; e < 32 * 262; e += 128) {
            int ci = e / 262, jj = e - ci * 262;
            int l = l0 - 3 + jj;
            float v = 0.f;
            if (l >= 0 && l < LL) {
                v = in[((size_t)b * CIN + cb + ci) * LL + l];
                if (BNIN) v = fmaxf(v * scA[cb + ci] + shA[cb + ci], 0.f);
            }
            xs[ci][jj] = v;
        }
        for (int e = tid; e < 8 * 32 * 7; e += 128) {
            int co = e / 224, r = e - co * 224;
            int ci = r / 7, k = r - ci * 7;
            ws[co][ci][k] = w[((size_t)(co0 + co) * CIN + cb + ci) * 7 + k];
        }
        __syncthreads();
        for (int ci = 0; ci < 32; ci++) {
#pragma unroll
            for (int k = 0; k < 7; k++) {
                float x0 = xs[ci][tid + k];
                float x1 = xs[ci][tid + 128 + k];
#pragma unroll
                for (int co = 0; co < 8; co++) {
                    float wv = ws[co][ci][k];
                    acc[co][0] = fmaf(x0, wv, acc[co][0]);
                    acc[co][1] = fmaf(x1, wv, acc[co][1]);
                }
            }
        }
    }
#pragma unroll
    for (int co = 0; co < 8; co++) {
        out[((size_t)b * Cout + co0 + co) * LL + l0 + tid]       = acc[co][0];
        out[((size_t)b * Cout + co0 + co) * LL + l0 + 128 + tid] = acc[co][1];
    }
    const int lane = tid & 31, wd = tid >> 5;
#pragma unroll
    for (int co = 0; co < 8; co++) {
        float s = acc[co][0] + acc[co][1];
        float q = acc[co][0] * acc[co][0] + acc[co][1] * acc[co][1];
#pragma unroll
        for (int o = 16; o > 0; o >>= 1) {
            s += __shfl_down_sync(0xFFFFFFFFu, s, o);
            q += __shfl_down_sync(0xFFFFFFFFu, q, o);
        }
        if (lane == 0) { wred_s[wd][co] = s; wred_q[wd][co] = q; }
    }
    __syncthreads();
    if (tid < 8) {
        float S = 0.f, Q = 0.f;
#pragma unroll
        for (int ww = 0; ww < 4; ww++) { S += wred_s[ww][tid]; Q += wred_q[ww][tid]; }
        atomicAdd(&sumOut[co0 + tid], S);
        atomicAdd(&sqOut[co0 + tid], Q);
    }
}

// ---------------- launch 1: persistent conv stack (3 internal grid syncs) ----
__global__ __launch_bounds__(128) void conv_all_k(
    const float* __restrict__ c1w, const float* __restrict__ g1, const float* __restrict__ b1,
    const float* __restrict__ c2w, const float* __restrict__ g2, const float* __restrict__ b2,
    const float* __restrict__ c3w, const float* __restrict__ g3, const float* __restrict__ b3)
{
    __shared__ float xs[32][264];
    __shared__ float ws[8][32][8];
    __shared__ float scA[64], shA[64];
    __shared__ float wred_s[4][8], wred_q[4][8];
    __shared__ float sc3[256], sh3[256];

    const int bid = blockIdx.x, tid = threadIdx.x;
    int csn = 0;
    const float invN = 1.f / (float)(BB * LL);

#define CBAR() do {                                                            \
    __threadfence(); __syncthreads();                                          \
    bool last_ = false;                                                        \
    if (tid == 0) last_ = (atomicAdd(&g_cbar_cnt, 1) == NCONV - 1);            \
    if (tid == 0 && last_) {                                                   \
        g_cbar_cnt = 0; __threadfence();                                       \
        atomicExch(&g_cbar_sen, csn ^ 1);                                      \
    }                                                                          \
    if (tid == 0 && !last_) {                                                  \
        while (*((volatile int*)&g_cbar_sen) != (csn ^ 1)) __nanosleep(64);    \
    }                                                                          \
    __syncthreads(); csn ^= 1;                                                 \
} while (0)

    // phase 1: conv1 (32->32), 2048 tiles
    for (int tile = bid; tile < 2048; tile += NCONV) {
        int l0 = (tile & 3) * 256, b = (tile >> 2) & 127, co0 = (tile >> 9) * 8;
        conv_tile<false>(g_t0, c1w, 32, 32, l0, b, co0, g_a,
                         nullptr, nullptr, g_s1, g_q1, xs, ws, wred_s, wred_q);
    }
    CBAR();
    // phase 2: conv2 (32->64) with bn1+relu on load, 4096 tiles
    if (tid < 32) {
        float mean = g_s1[tid] * invN;
        float var  = g_q1[tid] * invN - mean * mean;
        float s = g1[tid] * rsqrtf(var + 1e-5f);
        scA[tid] = s; shA[tid] = b1[tid] - mean * s;
    }
    __syncthreads();
    for (int tile = bid; tile < 4096; tile += NCONV) {
        int l0 = (tile & 3) * 256, b = (tile >> 2) & 127, co0 = (tile >> 9) * 8;
        conv_tile<true>(g_a, c2w, 32, 64, l0, b, co0, g_y,
                        scA, shA, g_s2, g_q2, xs, ws, wred_s, wred_q);
    }
    CBAR();
    // phase 3: conv3 (64->256) with bn2+relu on load, 16384 tiles
    if (tid < 64) {
        float mean = g_s2[tid] * invN;
        float var  = g_q2[tid] * invN - mean * mean;
        float s = g2[tid] * rsqrtf(var + 1e-5f);
        scA[tid] = s; shA[tid] = b2[tid] - mean * s;
    }
    __syncthreads();
    for (int tile = bid; tile < 16384; tile += NCONV) {
        int l0 = (tile & 3) * 256, b = (tile >> 2) & 127, co0 = (tile >> 9) * 8;
        conv_tile<true>(g_y, c3w, 64, 256, l0, b, co0, g_z,
                        scA, shA, g_s3, g_q3, xs, ws, wred_s, wred_q);
    }
    CBAR();
    // phase 4: bn3 + relu + transpose -> g_X
#pragma unroll
    for (int r = 0; r < 2; r++) {
        int c = tid + r * 128;
        float mean = g_s3[c] * invN;
        float var  = g_q3[c] * invN - mean * mean;
        float s = g3[c] * rsqrtf(var + 1e-5f);
        sc3[c] = s; sh3[c] = b3[c] - mean * s;
    }
    __syncthreads();
    for (size_t e = (size_t)bid * 128 + tid; e < (size_t)BB * 256 * LL;
         e += (size_t)NCONV * 128) {
        int l = (int)(e & (LL - 1));
        size_t bc = e >> 10;
        int c = (int)(bc & 255);
        int b = (int)(bc >> 8);
        float v = fmaxf(g_z[e] * sc3[c] + sh3[c], 0.f);
        g_X[((size_t)b * LL + l) * 256 + c] = v;
    }
#undef CBAR
}

// ---------------------------------------------------------------------------
// Persistent LSTM sequence kernel. grid (38,4) = 152 CTAs (bx>=32 exit fast;
// grid>=148 dodges the low-grid SM-issue throttle). 128 threads, 1 CTA/SM.
// CTA tile: 32 rows x 64 gate cols. K=768 in 12 chunks of 64. Weights SMEM-
// resident. FFMA2 inner product. c register-resident. Per-row-group barrier;
// next step's x-only chunks (0-3) computed in the barrier shadow.
// ---------------------------------------------------------------------------
template<bool PROJ>
__global__ __launch_bounds__(128) void lstm_seq_k(
    int hbase,
    const float* __restrict__ Wih, const float* __restrict__ Whh,
    const float* __restrict__ bih, const float* __restrict__ bhh,
    const float* __restrict__ outW, const float* __restrict__ outb,
    float* __restrict__ outBuf)
{
    if (blockIdx.x >= 32) return;

    extern __shared__ float smf[];
    float* Bsw = smf;                    // [768][64] weight tile (192KB)
    float* Asb = smf + 768 * 64;         // [2][32][64] A double buffer (16KB)
    float* gb  = Asb + 2 * 2048;         // [64] pre-added bias
    float* Pw  = gb + 64;                // [8][516] proj weights (PROJ)
    float* ob  = Pw + 8 * 516;           // [8] proj bias (PROJ)
    float (*Gs)[80] = (float(*)[80])Asb; // gates staging (aliases Asb)

    const int tid = threadIdx.x;
    const int bx = blockIdx.x, by = blockIdx.y;
    const int n0 = bx * 16, m0 = by * 32;
    const int tx = tid & 15, ty = tid >> 4;

    // ---- one-time fills ----
    for (int e = tid * 4; e < 768 * 64; e += 512) {
        int col = e / 768, k = e % 768;
        int jr = (col >> 4) * HSZ + n0 + (col & 15);
        float4 w = (k < 256) ? *(const float4*)(Wih + (size_t)jr * 256 + k)
                             : *(const float4*)(Whh + (size_t)jr * HSZ + (k - 256));
        Bsw[(k + 0) * 64 + col] = w.x;
        Bsw[(k + 1) * 64 + col] = w.y;
        Bsw[(k + 2) * 64 + col] = w.z;
        Bsw[(k + 3) * 64 + col] = w.w;
    }
    if (tid < 64)
        gb[tid] = bih[(tid >> 4) * HSZ + n0 + (tid & 15)]
                + bhh[(tid >> 4) * HSZ + n0 + (tid & 15)];
    if constexpr (PROJ) {
        for (int e = tid; e < 8 * 512; e += 128) {
            int q = e >> 9, k = e & 511;
            Pw[q * 516 + k] = outW[(size_t)(bx * 8 + q) * HSZ + k];
        }
        if (tid < 8) ob[tid] = outb[bx * 8 + tid];
    }
    __syncthreads();

    // register-resident c: element rr -> row=(tid+rr*128)>>4, nn=(tid+rr*128)&15
    float creg[4];
#pragma unroll
    for (int rr = 0; rr < 4; rr++) {
        if (PROJ) {
            int e = tid + rr * 128;
            creg[rr] = g_c[(m0 + (e >> 4)) * HSZ + n0 + (e & 15)];
        } else creg[rr] = 0.f;
    }

    float ra[16];
#define LOADA_X(kb, t) do {                                                    \
    _Pragma("unroll")                                                          \
    for (int j = 0; j < 16; j++) {                                             \
        int e = tid + j * 128;                                                 \
        ra[j] = g_X[((size_t)(m0 + (e >> 6)) * LL + (t)) * 256                 \
                    + (kb) * 64 + (e & 63)];                                   \
    }                                                                          \
} while (0)
#define LOADA_H(kb, hp) do {                                                   \
    _Pragma("unroll")                                                          \
    for (int j = 0; j < 16; j++) {                                             \
        int e = tid + j * 128;                                                 \
        ra[j] = __ldcg((hp) + (m0 + (e >> 6)) * HSZ + ((kb) - 4) * 64 + (e & 63)); \
    }                                                                          \
} while (0)
#define STOREA(pb) do {                                                        \
    _Pragma("unroll")                                                          \
    for (int j = 0; j < 16; j++) {                                             \
        int e = tid + j * 128;                                                 \
        Asb[(pb) * 2048 + (e >> 6) * 64 + (e & 63)] = ra[j];                   \
    }                                                                          \
} while (0)

    ull acc2[4][2];
    float pa0 = 0.f, pa1 = 0.f;

#define COMPUTE(pb, kb) do {                                                   \
    const float* Ar = Asb + (pb) * 2048;                                       \
    const float* Br = Bsw + (size_t)(kb) * 4096 + tx * 4;                      \
    _Pragma("unroll")                                                          \
    for (int k4 = 0; k4 < 64; k4 += 4) {                                       \
        float4 av0 = *(const float4*)(Ar + (ty * 4 + 0) * 64 + k4);            \
        float4 av1 = *(const float4*)(Ar + (ty * 4 + 1) * 64 + k4);            \
        float4 av2 = *(const float4*)(Ar + (ty * 4 + 2) * 64 + k4);            \
        float4 av3 = *(const float4*)(Ar + (ty * 4 + 3) * 64 + k4);            \
        _Pragma("unroll")                                                      \
        for (int u = 0; u < 4; u++) {                                          \
            ulonglong2 bv = *(const ulonglong2*)(Br + (size_t)(k4 + u) * 64);  \
            float a0_ = (u == 0 ? av0.x : u == 1 ? av0.y : u == 2 ? av0.z : av0.w); \
            float a1_ = (u == 0 ? av1.x : u == 1 ? av1.y : u == 2 ? av1.z : av1.w); \
            float a2_ = (u == 0 ? av2.x : u == 1 ? av2.y : u == 2 ? av2.z : av2.w); \
            float a3_ = (u == 0 ? av3.x : u == 1 ? av3.y : u == 2 ? av3.z : av3.w); \
            ull p0_, p1_, p2_, p3_;                                            \
            asm("mov.b64 %0, {%1, %1};" : "=l"(p0_) : "f"(a0_));               \
            asm("mov.b64 %0, {%1, %1};" : "=l"(p1_) : "f"(a1_));               \
            asm("mov.b64 %0, {%1, %1};" : "=l"(p2_) : "f"(a2_));               \
            asm("mov.b64 %0, {%1, %1};" : "=l"(p3_) : "f"(a3_));               \
            asm("fma.rn.f32x2 %0, %1, %2, %0;" : "+l"(acc2[0][0]) : "l"(p0_), "l"(bv.x)); \
            asm("fma.rn.f32x2 %0, %1, %2, %0;" : "+l"(acc2[0][1]) : "l"(p0_), "l"(bv.y)); \
            asm("fma.rn.f32x2 %0, %1, %2, %0;" : "+l"(acc2[1][0]) : "l"(p1_), "l"(bv.x)); \
            asm("fma.rn.f32x2 %0, %1, %2, %0;" : "+l"(acc2[1][1]) : "l"(p1_), "l"(bv.y)); \
            asm("fma.rn.f32x2 %0, %1, %2, %0;" : "+l"(acc2[2][0]) : "l"(p2_), "l"(bv.x)); \
            asm("fma.rn.f32x2 %0, %1, %2, %0;" : "+l"(acc2[2][1]) : "l"(p2_), "l"(bv.y)); \
            asm("fma.rn.f32x2 %0, %1, %2, %0;" : "+l"(acc2[3][0]) : "l"(p3_), "l"(bv.x)); \
            asm("fma.rn.f32x2 %0, %1, %2, %0;" : "+l"(acc2[3][1]) : "l"(p3_), "l"(bv.y)); \
        }                                                                      \
    }                                                                          \
} while (0)

#define PROJACC(pb, kb) do {                                                   \
    const int prow_ = tid >> 3, q_ = tid & 7;                                  \
    const float* Ar = Asb + (pb) * 2048;                                       \
    const float* Pq = Pw + q_ * 516 + ((kb) - 4) * 64;                         \
    _Pragma("unroll")                                                          \
    for (int kk = 0; kk < 64; kk += 4) {                                       \
        float4 w4 = *(const float4*)(Pq + kk);                                 \
        float4 a0 = *(const float4*)(Ar + prow_ * 64 + kk);                    \
        float4 a1 = *(const float4*)(Ar + (prow_ + 16) * 64 + kk);             \
        pa0 = fmaf(a0.x, w4.x, pa0); pa0 = fmaf(a0.y, w4.y, pa0);              \
        pa0 = fmaf(a0.z, w4.z, pa0); pa0 = fmaf(a0.w, w4.w, pa0);              \
        pa1 = fmaf(a1.x, w4.x, pa1); pa1 = fmaf(a1.y, w4.y, pa1);              \
        pa1 = fmaf(a1.z, w4.z, pa1); pa1 = fmaf(a1.w, w4.w, pa1);              \
    }                                                                          \
} while (0)

    int p = 0, ls = 0;
    // ---- x-part of step 0 (h not needed) ----
#pragma unroll
    for (int r = 0; r < 4; r++) { acc2[r][0] = 0ull; acc2[r][1] = 0ull; }
    LOADA_X(0, PROJ ? (LL - 1) : 0);
    for (int kb = 0; kb < 4; kb++) {
        STOREA(p); __syncthreads();
        if (kb < 3) LOADA_X(kb + 1, PROJ ? (LL - 1) : 0);
        COMPUTE(p, kb);
        p ^= 1;
    }

    for (int s = 0; s < LL; s++) {
        const int t = PROJ ? (LL - 1 - s) : s;
        const float* hin = g_h[(hbase + s) % 3];
        float* hout      = g_h[(hbase + s + 1) % 3];

        if (s > 0) {   // wait for h(s)
            if (tid == 0) {
                while (*((volatile int*)&g_bar_sen[by]) != (ls ^ 1)) __nanosleep(32);
            }
            __syncthreads();
            ls ^= 1;
        }

        // ---- h-part: chunks 4..11 ----
        pa0 = 0.f; pa1 = 0.f;
        LOADA_H(4, hin);
        for (int kb = 4; kb < 12; kb++) {
            STOREA(p); __syncthreads();
            if (kb < 11) LOADA_H(kb + 1, hin);
            if (PROJ) PROJACC(p, kb);
            COMPUTE(p, kb);
            p ^= 1;
        }

        // ---- stage gates, apply cell ----
        __syncthreads();
#pragma unroll
        for (int r = 0; r < 4; r++) {
            float lo0, hi0, lo1, hi1;
            asm("mov.b64 {%0, %1}, %2;" : "=f"(lo0), "=f"(hi0) : "l"(acc2[r][0]));
            asm("mov.b64 {%0, %1}, %2;" : "=f"(lo1), "=f"(hi1) : "l"(acc2[r][1]));
            Gs[ty * 4 + r][tx * 4 + 0] = lo0;
            Gs[ty * 4 + r][tx * 4 + 1] = hi0;
            Gs[ty * 4 + r][tx * 4 + 2] = lo1;
            Gs[ty * 4 + r][tx * 4 + 3] = hi1;
        }
        __syncthreads();

#pragma unroll
        for (int rr = 0; rr < 4; rr++) {
            int e = tid + rr * 128;
            int row = e >> 4, nn = e & 15;
            float gi = Gs[row][nn]      + gb[nn];
            float gf = Gs[row][16 + nn] + gb[16 + nn];
            float gg = Gs[row][32 + nn] + gb[32 + nn];
            float go = Gs[row][48 + nn] + gb[48 + nn];
            float iv = 1.f / (1.f + __expf(-gi));
            float fv = 1.f / (1.f + __expf(-gf));
            float gv = tanh_fast(gg);
            float ov = 1.f / (1.f + __expf(-go));
            float cn = fv * creg[rr] + iv * gv;
            creg[rr] = cn;
            hout[(m0 + row) * HSZ + n0 + nn] = ov * tanh_fast(cn);
        }
        if constexpr (PROJ) {
            const int prow = tid >> 3, q = tid & 7;
            float bo = ob[q];
            outBuf[((size_t)(m0 + prow) * LL + t) * 256 + bx * 8 + q]      = pa0 + bo;
            outBuf[((size_t)(m0 + prow + 16) * LL + t) * 256 + bx * 8 + q] = pa1 + bo;
        }

        // ---- arrive (every step: keeps sense parity even) ----
        __threadfence();
        __syncthreads();
        if (tid == 0) {
            if (atomicAdd(&g_bar_cnt[by], 1) == 31) {
                g_bar_cnt[by] = 0;
                __threadfence();
                atomicExch(&g_bar_sen[by], ls ^ 1);
            }
        }

        // ---- barrier shadow: x-part of step s+1 ----
        if (s < LL - 1) {
            const int tn = PROJ ? (LL - 2 - s) : (s + 1);
#pragma unroll
            for (int r = 0; r < 4; r++) { acc2[r][0] = 0ull; acc2[r][1] = 0ull; }
            LOADA_X(0, tn);
            for (int kb = 0; kb < 4; kb++) {
                STOREA(p); __syncthreads();
                if (kb < 3) LOADA_X(kb + 1, tn);
                COMPUTE(p, kb);
                p ^= 1;
            }
        }
    }

    if constexpr (!PROJ) {
#pragma unroll
        for (int rr = 0; rr < 4; rr++) {
            int e = tid + rr * 128;
            g_c[(m0 + (e >> 4)) * HSZ + n0 + (e & 15)] = creg[rr];
        }
    }
#undef LOADA_X
#undef LOADA_H
#undef STOREA
#undef COMPUTE
#undef PROJACC
}

// ---------------------------------------------------------------------------
extern "C" void kernel_launch(void* const* d_in, const int* in_sizes, int n_in,
                              void* d_out, int out_size) {
    const float* xin     = (const float*)d_in[0];
    const float* conv1_w = (const float*)d_in[1];
    const float* bn1_g   = (const float*)d_in[2];
    const float* bn1_b   = (const float*)d_in[3];
    const float* conv2_w = (const float*)d_in[4];
    const float* bn2_g   = (const float*)d_in[5];
    const float* bn2_b   = (const float*)d_in[6];
    const float* conv3_w = (const float*)d_in[7];
    const float* bn3_g   = (const float*)d_in[8];
    const float* bn3_b   = (const float*)d_in[9];
    const float* eWih0   = (const float*)d_in[10];
    const float* eWhh0   = (const float*)d_in[11];
    const float* ebih0   = (const float*)d_in[12];
    const float* ebhh0   = (const float*)d_in[13];
    // d_in[14..17] encoder layer-1: provably dead (never reaches the output)
    const float* dWih0   = (const float*)d_in[18];
    const float* dWhh0   = (const float*)d_in[19];
    const float* dbih0   = (const float*)d_in[20];
    const float* dbhh0   = (const float*)d_in[21];
    // d_in[22..25] decoder layer-1: provably dead
    const float* outW    = (const float*)d_in[26];
    const float* outb    = (const float*)d_in[27];
    float* out = (float*)d_out;

    const int ENC_SM = (768 * 64 + 2 * 2048 + 64) * 4;                  // 213,248 B
    const int DEC_SM = (768 * 64 + 2 * 2048 + 64 + 8 * 516 + 8) * 4;    // 229,792 B
    cudaFuncSetAttribute(lstm_seq_k<false>, cudaFuncAttributeMaxDynamicSharedMemorySize, ENC_SM);
    cudaFuncSetAttribute(lstm_seq_k<true>,  cudaFuncAttributeMaxDynamicSharedMemorySize, DEC_SM);

    // launch 0: zero + transpose
    prep0_k<<<(BB * LL * 32 + 255) / 256, 256>>>(xin);
    // launch 1: full conv/BN stack, persistent
    conv_all_k<<<NCONV, 128>>>(conv1_w, bn1_g, bn1_b,
                               conv2_w, bn2_g, bn2_b,
                               conv3_w, bn3_g, bn3_b);
    // launch 2: encoder (1024 steps persistent). h starts in g_h[0].
    lstm_seq_k<false><<<dim3(38, 4), 128, ENC_SM>>>(0, eWih0, eWhh0, ebih0, ebhh0,
                                                    nullptr, nullptr, nullptr);
    // launch 3: decoder (profiled slot). h lives in g_h[1024 % 3] = g_h[1].
    lstm_seq_k<true><<<dim3(38, 4), 128, DEC_SM>>>(1, dWih0, dWhh0, dbih0, dbhh0,
                                                   outW, outb, out);
}